// round 14
// baseline (speedup 1.0000x reference)
#include <cuda_runtime.h>
#include <math.h>

#define B_    8
#define T_    2048
#define DIN   512
#define DA    8
#define DOUT  512
#define NCAP  384         // survivor cap for the sparse gather path
#define THR   16.0f       // exp(-16) ~ 1.1e-7 dropped-per-key bound
#define DGRP  16          // dense queries per group
#define NSPLIT 4          // column quarters per group
#define DGRID 512         // persistent dense CTAs

__device__ __align__(16) float g_Q[B_ * T_ * DA];
__device__ __align__(16) float g_K[B_ * T_ * DA];
__device__ __align__(16) float g_V[B_ * T_ * DOUT];
__device__ float g_m[B_ * T_];          // per-query max of d^8
__device__ int   g_dcount[B_];          // dense-queue counts
__device__ int   g_dq[B_ * T_];         // dense-queue (local q indices per batch)
__device__ int   g_units[B_ * (T_ / DGRP) * NSPLIT + 64];
__device__ int   g_nunits;
__device__ int   g_ticket;

// ---------------------------------------------------------------------------
// f32x2 packed helpers
// ---------------------------------------------------------------------------
__device__ __forceinline__ unsigned long long pack2(float lo, float hi) {
    unsigned long long d;
    asm("mov.b64 %0, {%1, %2};" : "=l"(d) : "f"(lo), "f"(hi));
    return d;
}
__device__ __forceinline__ unsigned long long fma2(unsigned long long a,
                                                   unsigned long long b,
                                                   unsigned long long c) {
    unsigned long long d;
    asm("fma.rn.f32x2 %0, %1, %2, %3;" : "=l"(d) : "l"(a), "l"(b), "l"(c));
    return d;
}
__device__ __forceinline__ void unpack2(unsigned long long v, float& lo, float& hi) {
    asm("mov.b64 {%0, %1}, %2;" : "=f"(lo), "=f"(hi) : "l"(v));
}

// ---------------------------------------------------------------------------
__global__ void plan_kernel() {
    if (threadIdx.x != 0) return;
    int total = 0;
    for (int b = 0; b < B_; b++) {
        int cnt = g_dcount[b];
        int groups = (cnt + DGRP - 1) / DGRP;
        for (int g = 0; g < groups; g++)
            for (int cq = 0; cq < NSPLIT; cq++)
                g_units[total++] = (b << 16) | (g << 4) | cq;
    }
    g_nunits = total;
    g_ticket = 0;
}

// ---------------------------------------------------------------------------
// V = X @ Wv with packed f32x2 FMAs (measured ~170us). Also zeroes the
// dense-queue counters (runs before attn_sparse in the same stream).
// ---------------------------------------------------------------------------
__global__ __launch_bounds__(256, 2) void vproj_kernel(const float* __restrict__ A,
                                                       const float* __restrict__ Bw) {
    __shared__ float As[16][132];
    __shared__ float Bs[16][128];

    int t  = threadIdx.x;
    int bm = blockIdx.y;
    int bn = blockIdx.x;
    int tr = t >> 4;
    int tc = t & 15;

    if (bm == 0 && bn == 0 && t < B_) g_dcount[t] = 0;

    const float* Ag = A + (size_t)bm * 128 * DIN;
    const float* Bg = Bw + (size_t)bn * 128;

    unsigned long long acc2[4][8];
#pragma unroll
    for (int p = 0; p < 4; p++)
#pragma unroll
        for (int j = 0; j < 8; j++) acc2[p][j] = 0ull;

    for (int kt = 0; kt < DIN; kt += 16) {
#pragma unroll
        for (int e = t; e < 512; e += 256) {
            int row = e >> 2;
            int cg  = (e & 3) << 2;
            float4 v = *(const float4*)(Ag + (size_t)row * DIN + kt + cg);
            As[cg + 0][row] = v.x;
            As[cg + 1][row] = v.y;
            As[cg + 2][row] = v.z;
            As[cg + 3][row] = v.w;
        }
#pragma unroll
        for (int e = t; e < 512; e += 256) {
            int row = e >> 5;
            int cg  = (e & 31) << 2;
            *(float4*)(&Bs[row][cg]) =
                *(const float4*)(Bg + (size_t)(kt + row) * DOUT + cg);
        }
        __syncthreads();

#pragma unroll
        for (int k = 0; k < 16; k++) {
            ulonglong2 a01 = *(const ulonglong2*)(&As[k][tr * 4]);
            ulonglong2 a23 = *(const ulonglong2*)(&As[k][tr * 4 + 64]);
            float4 bA = *(const float4*)(&Bs[k][tc * 4]);
            float4 bB = *(const float4*)(&Bs[k][tc * 4 + 64]);
            unsigned long long a2[4] = {a01.x, a01.y, a23.x, a23.y};
            unsigned long long b2[8];
            b2[0] = pack2(bA.x, bA.x); b2[1] = pack2(bA.y, bA.y);
            b2[2] = pack2(bA.z, bA.z); b2[3] = pack2(bA.w, bA.w);
            b2[4] = pack2(bB.x, bB.x); b2[5] = pack2(bB.y, bB.y);
            b2[6] = pack2(bB.z, bB.z); b2[7] = pack2(bB.w, bB.w);
#pragma unroll
            for (int p = 0; p < 4; p++)
#pragma unroll
                for (int j = 0; j < 8; j++)
                    acc2[p][j] = fma2(a2[p], b2[j], acc2[p][j]);
        }
        __syncthreads();
    }

#pragma unroll
    for (int p = 0; p < 4; p++) {
        int r0 = tr * 4 + (p >> 1) * 64 + (p & 1) * 2;
        float lo[8], hi[8];
#pragma unroll
        for (int j = 0; j < 8; j++) unpack2(acc2[p][j], lo[j], hi[j]);
        float* c0 = g_V + (size_t)(bm * 128 + r0) * DOUT + bn * 128;
        float* c1 = c0 + DOUT;
        *(float4*)(c0 + tc * 4)      = make_float4(lo[0], lo[1], lo[2], lo[3]);
        *(float4*)(c0 + tc * 4 + 64) = make_float4(lo[4], lo[5], lo[6], lo[7]);
        *(float4*)(c1 + tc * 4)      = make_float4(hi[0], hi[1], hi[2], hi[3]);
        *(float4*)(c1 + tc * 4 + 64) = make_float4(hi[4], hi[5], hi[6], hi[7]);
    }
}

// ---------------------------------------------------------------------------
// Q,K projections (measured ~35us). R10-exact (interleaved g_K layout).
// ---------------------------------------------------------------------------
__global__ __launch_bounds__(256) void qk_kernel(const float* __restrict__ X,
                                                 const float* __restrict__ Wq,
                                                 const float* __restrict__ Wk) {
    int warp = threadIdx.x >> 5;
    int lane = threadIdx.x & 31;
    int tok0 = blockIdx.x * 32 + warp * 4;

    float aq[4][8], ak[4][8];
#pragma unroll
    for (int t = 0; t < 4; t++)
#pragma unroll
        for (int f = 0; f < 8; f++) { aq[t][f] = 0.f; ak[t][f] = 0.f; }

#pragma unroll 4
    for (int d = lane; d < DIN; d += 32) {
        float xv[4];
#pragma unroll
        for (int t = 0; t < 4; t++) xv[t] = X[(size_t)(tok0 + t) * DIN + d];
        float4 q0 = *(const float4*)(Wq + (size_t)d * 8);
        float4 q1 = *(const float4*)(Wq + (size_t)d * 8 + 4);
        float4 k0 = *(const float4*)(Wk + (size_t)d * 8);
        float4 k1 = *(const float4*)(Wk + (size_t)d * 8 + 4);
#pragma unroll
        for (int t = 0; t < 4; t++) {
            aq[t][0] += xv[t] * q0.x; aq[t][1] += xv[t] * q0.y;
            aq[t][2] += xv[t] * q0.z; aq[t][3] += xv[t] * q0.w;
            aq[t][4] += xv[t] * q1.x; aq[t][5] += xv[t] * q1.y;
            aq[t][6] += xv[t] * q1.z; aq[t][7] += xv[t] * q1.w;
            ak[t][0] += xv[t] * k0.x; ak[t][1] += xv[t] * k0.y;
            ak[t][2] += xv[t] * k0.z; ak[t][3] += xv[t] * k0.w;
            ak[t][4] += xv[t] * k1.x; ak[t][5] += xv[t] * k1.y;
            ak[t][6] += xv[t] * k1.z; ak[t][7] += xv[t] * k1.w;
        }
    }

#pragma unroll
    for (int t = 0; t < 4; t++) {
#pragma unroll
        for (int f = 0; f < 8; f++) {
#pragma unroll
            for (int off = 16; off >= 1; off >>= 1) {
                aq[t][f] += __shfl_xor_sync(0xffffffffu, aq[t][f], off);
                ak[t][f] += __shfl_xor_sync(0xffffffffu, ak[t][f], off);
            }
        }
        if (lane == 0) {
            float* qo = g_Q + (size_t)(tok0 + t) * 8;
            float* ko = g_K + (size_t)(tok0 + t) * 8;
            *(float4*)(qo)     = make_float4(aq[t][0], aq[t][1], aq[t][2], aq[t][3]);
            *(float4*)(qo + 4) = make_float4(aq[t][4], aq[t][5], aq[t][6], aq[t][7]);
            *(float4*)(ko)     = make_float4(ak[t][0], ak[t][1], ak[t][2], ak[t][3]);
            *(float4*)(ko + 4) = make_float4(ak[t][4], ak[t][5], ak[t][6], ak[t][7]);
        }
    }
}

// ---------------------------------------------------------------------------
// Sparse attention — R10 structure with the count pass FUSED into the
// gather: accumulate n += popc per chunk and bail to the dense queue the
// moment n exceeds NCAP (output untouched on bail; dense writes later).
// Sparse-path arithmetic is bit-identical to R10.
// ---------------------------------------------------------------------------
__global__ __launch_bounds__(256) void attn_sparse_kernel(float* __restrict__ Out) {
    int warp = threadIdx.x >> 5;
    int lane = threadIdx.x & 31;
    int q    = blockIdx.x * 8 + warp;
    int b    = q >> 11;
    const float* Kb = g_K + (size_t)b * T_ * DA;
    const float* Vb = g_V + (size_t)b * T_ * DOUT;

    float4 qa = *(const float4*)(g_Q + (size_t)q * DA);
    float4 qb = *(const float4*)(g_Q + (size_t)q * DA + 4);

    float s8v[64];
    float m = -INFINITY;

#pragma unroll 1
    for (int i = 0; i < 64; i++) {
        int s = i * 32 + lane;
        const float4* kp = (const float4*)(Kb + (size_t)s * DA);
        float4 k0 = kp[0];
        float4 k1 = kp[1];
        float d = qa.x * k0.x + qa.y * k0.y + qa.z * k0.z + qa.w * k0.w
                + qb.x * k1.x + qb.y * k1.y + qb.z * k1.z + qb.w * k1.w;
        float d2 = d * d;
        float d4 = d2 * d2;
        float d8 = d4 * d4;
        s8v[i] = d8;
        m = fmaxf(m, d8);
    }
#pragma unroll
    for (int off = 16; off >= 1; off >>= 1)
        m = fmaxf(m, __shfl_xor_sync(0xffffffffu, m, off));

    if (lane == 0) g_m[q] = m;

    float thr = m - THR;

    // Fused count + gather with bail-out
    float acc0 = 0.f, acc1 = 0.f, acc2 = 0.f, acc3 = 0.f;
    float acc4 = 0.f, acc5 = 0.f, acc6 = 0.f, acc7 = 0.f;
    float acc8 = 0.f, acc9 = 0.f, accA = 0.f, accB = 0.f;
    float accC = 0.f, accD = 0.f, accE = 0.f, accF = 0.f;
    float psum = 0.f;
    int   n    = 0;

#pragma unroll 1
    for (int i = 0; i < 64; i++) {
        float d8 = s8v[i];
        unsigned ball = __ballot_sync(0xffffffffu, d8 > thr);
        n += __popc(ball);
        if (n > NCAP) {
            if (lane == 0) {
                int idx = atomicAdd(&g_dcount[b], 1);
                g_dq[b * T_ + idx] = q & (T_ - 1);
            }
            return;                          // dense kernel overwrites Out
        }
        while (ball) {
            int src = __ffs(ball) - 1;
            ball &= ball - 1;
            float d8s = __shfl_sync(0xffffffffu, d8, src);
            float p = __expf(d8s - m);       // identical in all lanes
            psum += p;
            int s = i * 32 + src;
            const float4* vp = (const float4*)(Vb + (size_t)s * DOUT) + lane * 4;
            float4 v0 = vp[0];
            float4 v1 = vp[1];
            float4 v2 = vp[2];
            float4 v3 = vp[3];
            acc0 += p * v0.x; acc1 += p * v0.y; acc2 += p * v0.z; acc3 += p * v0.w;
            acc4 += p * v1.x; acc5 += p * v1.y; acc6 += p * v1.z; acc7 += p * v1.w;
            acc8 += p * v2.x; acc9 += p * v2.y; accA += p * v2.z; accB += p * v2.w;
            accC += p * v3.x; accD += p * v3.y; accE += p * v3.z; accF += p * v3.w;
        }
    }

    float inv = 1.f / psum;
    float4* op = (float4*)(Out + (size_t)q * DOUT) + lane * 4;
    op[0] = make_float4(acc0 * inv, acc1 * inv, acc2 * inv, acc3 * inv);
    op[1] = make_float4(acc4 * inv, acc5 * inv, acc6 * inv, acc7 * inv);
    op[2] = make_float4(acc8 * inv, acc9 * inv, accA * inv, accB * inv);
    op[3] = make_float4(accC * inv, accD * inv, accE * inv, accF * inv);
}

// ---------------------------------------------------------------------------
// Dense attention: ticket-queue persistent CTAs. R10-exact.
// ---------------------------------------------------------------------------
__global__ __launch_bounds__(256) void attn_dense_kernel(float* __restrict__ Out) {
    __shared__ float p_s[32][20];
    __shared__ float psum_s[DGRP];
    __shared__ int   qq_s[DGRP];
    __shared__ int   s_unit;

    int tid  = threadIdx.x;
    int warp = tid >> 5;
    int lane = tid & 31;

    while (true) {
        if (tid == 0) s_unit = atomicAdd(&g_ticket, 1);
        __syncthreads();
        int u = s_unit;
        if (u >= g_nunits) return;
        int enc = g_units[u];
        int b   = enc >> 16;
        int g   = (enc >> 4) & 0xFFF;
        int cq  = enc & 0xF;
        __syncthreads();

        int count = g_dcount[b];
        const float* Kb = g_K + (size_t)b * T_ * DA;
        const float* Vb = g_V + (size_t)b * T_ * DOUT;

        int ng = count - g * DGRP;
        if (ng > DGRP) ng = DGRP;

        if (tid < DGRP)
            qq_s[tid] = (tid < ng) ? g_dq[b * T_ + g * DGRP + tid] : 0;
        __syncthreads();

        int q0i = 2 * warp;
        int q1i = 2 * warp + 1;
        bool v0 = q0i < ng;
        bool v1 = q1i < ng;
        int gq0 = b * T_ + qq_s[v0 ? q0i : 0];
        int gq1 = b * T_ + qq_s[v1 ? q1i : 0];
        float qv0[8], qv1[8];
#pragma unroll
        for (int f = 0; f < 8; f++) {
            qv0[f] = g_Q[(size_t)gq0 * DA + f];
            qv1[f] = g_Q[(size_t)gq1 * DA + f];
        }
        float m0 = g_m[gq0];
        float m1 = g_m[gq1];
        float ps0 = 0.f, ps1 = 0.f;

        int col  = cq * 128 + warp * 16 + (lane & 15);
        int kpar = lane >> 4;
        float acc[DGRP];
#pragma unroll
        for (int j = 0; j < DGRP; j++) acc[j] = 0.f;

        for (int c = 0; c < T_ / 32; c++) {
            int k = c * 32 + lane;
            const float4* kp = (const float4*)(Kb + (size_t)k * DA);
            float4 k0 = kp[0];
            float4 k1 = kp[1];
            float d0 = qv0[0]*k0.x + qv0[1]*k0.y + qv0[2]*k0.z + qv0[3]*k0.w
                     + qv0[4]*k1.x + qv0[5]*k1.y + qv0[6]*k1.z + qv0[7]*k1.w;
            float d1 = qv1[0]*k0.x + qv1[1]*k0.y + qv1[2]*k0.z + qv1[3]*k0.w
                     + qv1[4]*k1.x + qv1[5]*k1.y + qv1[6]*k1.z + qv1[7]*k1.w;
            float e0 = d0 * d0; e0 = e0 * e0; e0 = e0 * e0;
            float e1 = d1 * d1; e1 = e1 * e1; e1 = e1 * e1;
            float p0 = v0 ? __expf(e0 - m0) : 0.f;
            float p1 = v1 ? __expf(e1 - m1) : 0.f;
            ps0 += p0;
            ps1 += p1;
            p_s[lane][q0i] = p0;
            p_s[lane][q1i] = p1;
            __syncthreads();

            const float* vptr = Vb + (size_t)(c * 32 + kpar) * DOUT + col;
#pragma unroll
            for (int kk2 = 0; kk2 < 16; kk2++) {
                int kk = 2 * kk2 + kpar;
                float v = vptr[(size_t)(2 * kk2) * DOUT];
                float pr[16];
                *(float4*)(pr)      = *(const float4*)(&p_s[kk][0]);
                *(float4*)(pr + 4)  = *(const float4*)(&p_s[kk][4]);
                *(float4*)(pr + 8)  = *(const float4*)(&p_s[kk][8]);
                *(float4*)(pr + 12) = *(const float4*)(&p_s[kk][12]);
#pragma unroll
                for (int j = 0; j < DGRP; j++)
                    acc[j] += pr[j] * v;
            }
            __syncthreads();
        }

#pragma unroll
        for (int off = 16; off >= 1; off >>= 1) {
            ps0 += __shfl_xor_sync(0xffffffffu, ps0, off);
            ps1 += __shfl_xor_sync(0xffffffffu, ps1, off);
        }
        if (lane == 0) {
            if (v0) psum_s[q0i] = ps0;
            if (v1) psum_s[q1i] = ps1;
        }
        __syncthreads();

#pragma unroll
        for (int j = 0; j < DGRP; j++)
            acc[j] += __shfl_xor_sync(0xffffffffu, acc[j], 16);

        if (kpar == 0) {
            for (int j = 0; j < ng; j++) {
                int gq = b * T_ + qq_s[j];
                Out[(size_t)gq * DOUT + col] = acc[j] / psum_s[j];
            }
        }
        __syncthreads();
    }
}

// ---------------------------------------------------------------------------
extern "C" void kernel_launch(void* const* d_in, const int* in_sizes, int n_in,
                              void* d_out, int out_size) {
    (void)in_sizes; (void)n_in; (void)out_size;
    const float* X  = (const float*)d_in[0];
    const float* Wq = (const float*)d_in[1];
    const float* Wk = (const float*)d_in[2];
    const float* Wv = (const float*)d_in[3];
    float* Out = (float*)d_out;

    vproj_kernel<<<dim3(DOUT / 128, (B_ * T_) / 128), 256>>>(X, Wv);
    qk_kernel<<<(B_ * T_) / 32, 256>>>(X, Wq, Wk);
    attn_sparse_kernel<<<(B_ * T_) / 8, 256>>>(Out);
    plan_kernel<<<1, 32>>>();
    attn_dense_kernel<<<DGRID, 256>>>(Out);
}

// round 15
// speedup vs baseline: 1.1723x; 1.1723x over previous
#include <cuda_runtime.h>
#include <math.h>

#define B_    8
#define T_    2048
#define DIN   512
#define DA    8
#define DOUT  512
#define NCAP  192         // survivor cap: dense path is cheaper above ~128
#define THR   16.0f       // exp(-16) ~ 1.1e-7 dropped-per-key bound
#define DGRP  16          // dense queries per group
#define NSPLIT 4          // column quarters per group
#define DGRID 512         // persistent dense CTAs

__device__ __align__(16) float g_Q[B_ * T_ * DA];
__device__ __align__(16) float g_K[B_ * T_ * DA];
__device__ __align__(16) float g_V[B_ * T_ * DOUT];
__device__ float g_m[B_ * T_];          // per-query max of d^8
__device__ int   g_dcount[B_];          // dense-queue counts
__device__ int   g_dq[B_ * T_];         // dense-queue (local q indices per batch)
__device__ int   g_units[B_ * (T_ / DGRP) * NSPLIT + 64];
__device__ int   g_nunits;
__device__ int   g_ticket;

// ---------------------------------------------------------------------------
// f32x2 packed helpers
// ---------------------------------------------------------------------------
__device__ __forceinline__ unsigned long long pack2(float lo, float hi) {
    unsigned long long d;
    asm("mov.b64 %0, {%1, %2};" : "=l"(d) : "f"(lo), "f"(hi));
    return d;
}
__device__ __forceinline__ unsigned long long fma2(unsigned long long a,
                                                   unsigned long long b,
                                                   unsigned long long c) {
    unsigned long long d;
    asm("fma.rn.f32x2 %0, %1, %2, %3;" : "=l"(d) : "l"(a), "l"(b), "l"(c));
    return d;
}
__device__ __forceinline__ void unpack2(unsigned long long v, float& lo, float& hi) {
    asm("mov.b64 {%0, %1}, %2;" : "=f"(lo), "=f"(hi) : "l"(v));
}

// ---------------------------------------------------------------------------
__global__ void plan_kernel() {
    if (threadIdx.x != 0) return;
    int total = 0;
    for (int b = 0; b < B_; b++) {
        int cnt = g_dcount[b];
        int groups = (cnt + DGRP - 1) / DGRP;
        for (int g = 0; g < groups; g++)
            for (int cq = 0; cq < NSPLIT; cq++)
                g_units[total++] = (b << 16) | (g << 4) | cq;
    }
    g_nunits = total;
    g_ticket = 0;
}

// ---------------------------------------------------------------------------
// V = X @ Wv with packed f32x2 FMAs (measured ~170us). Also zeroes the
// dense-queue counters (runs before attn_sparse in the same stream).
// ---------------------------------------------------------------------------
__global__ __launch_bounds__(256, 2) void vproj_kernel(const float* __restrict__ A,
                                                       const float* __restrict__ Bw) {
    __shared__ float As[16][132];
    __shared__ float Bs[16][128];

    int t  = threadIdx.x;
    int bm = blockIdx.y;
    int bn = blockIdx.x;
    int tr = t >> 4;
    int tc = t & 15;

    if (bm == 0 && bn == 0 && t < B_) g_dcount[t] = 0;

    const float* Ag = A + (size_t)bm * 128 * DIN;
    const float* Bg = Bw + (size_t)bn * 128;

    unsigned long long acc2[4][8];
#pragma unroll
    for (int p = 0; p < 4; p++)
#pragma unroll
        for (int j = 0; j < 8; j++) acc2[p][j] = 0ull;

    for (int kt = 0; kt < DIN; kt += 16) {
#pragma unroll
        for (int e = t; e < 512; e += 256) {
            int row = e >> 2;
            int cg  = (e & 3) << 2;
            float4 v = *(const float4*)(Ag + (size_t)row * DIN + kt + cg);
            As[cg + 0][row] = v.x;
            As[cg + 1][row] = v.y;
            As[cg + 2][row] = v.z;
            As[cg + 3][row] = v.w;
        }
#pragma unroll
        for (int e = t; e < 512; e += 256) {
            int row = e >> 5;
            int cg  = (e & 31) << 2;
            *(float4*)(&Bs[row][cg]) =
                *(const float4*)(Bg + (size_t)(kt + row) * DOUT + cg);
        }
        __syncthreads();

#pragma unroll
        for (int k = 0; k < 16; k++) {
            ulonglong2 a01 = *(const ulonglong2*)(&As[k][tr * 4]);
            ulonglong2 a23 = *(const ulonglong2*)(&As[k][tr * 4 + 64]);
            float4 bA = *(const float4*)(&Bs[k][tc * 4]);
            float4 bB = *(const float4*)(&Bs[k][tc * 4 + 64]);
            unsigned long long a2[4] = {a01.x, a01.y, a23.x, a23.y};
            unsigned long long b2[8];
            b2[0] = pack2(bA.x, bA.x); b2[1] = pack2(bA.y, bA.y);
            b2[2] = pack2(bA.z, bA.z); b2[3] = pack2(bA.w, bA.w);
            b2[4] = pack2(bB.x, bB.x); b2[5] = pack2(bB.y, bB.y);
            b2[6] = pack2(bB.z, bB.z); b2[7] = pack2(bB.w, bB.w);
#pragma unroll
            for (int p = 0; p < 4; p++)
#pragma unroll
                for (int j = 0; j < 8; j++)
                    acc2[p][j] = fma2(a2[p], b2[j], acc2[p][j]);
        }
        __syncthreads();
    }

#pragma unroll
    for (int p = 0; p < 4; p++) {
        int r0 = tr * 4 + (p >> 1) * 64 + (p & 1) * 2;
        float lo[8], hi[8];
#pragma unroll
        for (int j = 0; j < 8; j++) unpack2(acc2[p][j], lo[j], hi[j]);
        float* c0 = g_V + (size_t)(bm * 128 + r0) * DOUT + bn * 128;
        float* c1 = c0 + DOUT;
        *(float4*)(c0 + tc * 4)      = make_float4(lo[0], lo[1], lo[2], lo[3]);
        *(float4*)(c0 + tc * 4 + 64) = make_float4(lo[4], lo[5], lo[6], lo[7]);
        *(float4*)(c1 + tc * 4)      = make_float4(hi[0], hi[1], hi[2], hi[3]);
        *(float4*)(c1 + tc * 4 + 64) = make_float4(hi[4], hi[5], hi[6], hi[7]);
    }
}

// ---------------------------------------------------------------------------
// Q,K projections (measured ~35us). R10-exact.
// ---------------------------------------------------------------------------
__global__ __launch_bounds__(256) void qk_kernel(const float* __restrict__ X,
                                                 const float* __restrict__ Wq,
                                                 const float* __restrict__ Wk) {
    int warp = threadIdx.x >> 5;
    int lane = threadIdx.x & 31;
    int tok0 = blockIdx.x * 32 + warp * 4;

    float aq[4][8], ak[4][8];
#pragma unroll
    for (int t = 0; t < 4; t++)
#pragma unroll
        for (int f = 0; f < 8; f++) { aq[t][f] = 0.f; ak[t][f] = 0.f; }

#pragma unroll 4
    for (int d = lane; d < DIN; d += 32) {
        float xv[4];
#pragma unroll
        for (int t = 0; t < 4; t++) xv[t] = X[(size_t)(tok0 + t) * DIN + d];
        float4 q0 = *(const float4*)(Wq + (size_t)d * 8);
        float4 q1 = *(const float4*)(Wq + (size_t)d * 8 + 4);
        float4 k0 = *(const float4*)(Wk + (size_t)d * 8);
        float4 k1 = *(const float4*)(Wk + (size_t)d * 8 + 4);
#pragma unroll
        for (int t = 0; t < 4; t++) {
            aq[t][0] += xv[t] * q0.x; aq[t][1] += xv[t] * q0.y;
            aq[t][2] += xv[t] * q0.z; aq[t][3] += xv[t] * q0.w;
            aq[t][4] += xv[t] * q1.x; aq[t][5] += xv[t] * q1.y;
            aq[t][6] += xv[t] * q1.z; aq[t][7] += xv[t] * q1.w;
            ak[t][0] += xv[t] * k0.x; ak[t][1] += xv[t] * k0.y;
            ak[t][2] += xv[t] * k0.z; ak[t][3] += xv[t] * k0.w;
            ak[t][4] += xv[t] * k1.x; ak[t][5] += xv[t] * k1.y;
            ak[t][6] += xv[t] * k1.z; ak[t][7] += xv[t] * k1.w;
        }
    }

#pragma unroll
    for (int t = 0; t < 4; t++) {
#pragma unroll
        for (int f = 0; f < 8; f++) {
#pragma unroll
            for (int off = 16; off >= 1; off >>= 1) {
                aq[t][f] += __shfl_xor_sync(0xffffffffu, aq[t][f], off);
                ak[t][f] += __shfl_xor_sync(0xffffffffu, ak[t][f], off);
            }
        }
        if (lane == 0) {
            float* qo = g_Q + (size_t)(tok0 + t) * 8;
            float* ko = g_K + (size_t)(tok0 + t) * 8;
            *(float4*)(qo)     = make_float4(aq[t][0], aq[t][1], aq[t][2], aq[t][3]);
            *(float4*)(qo + 4) = make_float4(aq[t][4], aq[t][5], aq[t][6], aq[t][7]);
            *(float4*)(ko)     = make_float4(ak[t][0], ak[t][1], ak[t][2], ak[t][3]);
            *(float4*)(ko + 4) = make_float4(ak[t][4], ak[t][5], ak[t][6], ak[t][7]);
        }
    }
}

// ---------------------------------------------------------------------------
// Sparse attention — R10-exact structure: scan, max, SEPARATE count pass
// (popc only — dense queries skip the V gather entirely; this is load-
// bearing, see R14 regression), then gather. Count pass exits early once
// n > NCAP (strictly less work than R10).
// ---------------------------------------------------------------------------
__global__ __launch_bounds__(256) void attn_sparse_kernel(float* __restrict__ Out) {
    int warp = threadIdx.x >> 5;
    int lane = threadIdx.x & 31;
    int q    = blockIdx.x * 8 + warp;
    int b    = q >> 11;
    const float* Kb = g_K + (size_t)b * T_ * DA;
    const float* Vb = g_V + (size_t)b * T_ * DOUT;

    float4 qa = *(const float4*)(g_Q + (size_t)q * DA);
    float4 qb = *(const float4*)(g_Q + (size_t)q * DA + 4);

    float s8v[64];
    float m = -INFINITY;

#pragma unroll 1
    for (int i = 0; i < 64; i++) {
        int s = i * 32 + lane;
        const float4* kp = (const float4*)(Kb + (size_t)s * DA);
        float4 k0 = kp[0];
        float4 k1 = kp[1];
        float d = qa.x * k0.x + qa.y * k0.y + qa.z * k0.z + qa.w * k0.w
                + qb.x * k1.x + qb.y * k1.y + qb.z * k1.z + qb.w * k1.w;
        float d2 = d * d;
        float d4 = d2 * d2;
        float d8 = d4 * d4;
        s8v[i] = d8;
        m = fmaxf(m, d8);
    }
#pragma unroll
    for (int off = 16; off >= 1; off >>= 1)
        m = fmaxf(m, __shfl_xor_sync(0xffffffffu, m, off));

    if (lane == 0) g_m[q] = m;

    float thr = m - THR;

    // Count pass (popc only) with early exit
    int n = 0;
#pragma unroll 1
    for (int i = 0; i < 64; i++) {
        n += __popc(__ballot_sync(0xffffffffu, s8v[i] > thr));
        if (n > NCAP) break;
    }

    if (n > NCAP) {
        if (lane == 0) {
            int idx = atomicAdd(&g_dcount[b], 1);
            g_dq[b * T_ + idx] = q & (T_ - 1);
        }
        return;
    }

    // sparse gather
    float acc0 = 0.f, acc1 = 0.f, acc2 = 0.f, acc3 = 0.f;
    float acc4 = 0.f, acc5 = 0.f, acc6 = 0.f, acc7 = 0.f;
    float acc8 = 0.f, acc9 = 0.f, accA = 0.f, accB = 0.f;
    float accC = 0.f, accD = 0.f, accE = 0.f, accF = 0.f;
    float psum = 0.f;

#pragma unroll 1
    for (int i = 0; i < 64; i++) {
        float d8 = s8v[i];
        unsigned ball = __ballot_sync(0xffffffffu, d8 > thr);
        while (ball) {
            int src = __ffs(ball) - 1;
            ball &= ball - 1;
            float d8s = __shfl_sync(0xffffffffu, d8, src);
            float p = __expf(d8s - m);     // identical in all lanes
            psum += p;
            int s = i * 32 + src;
            const float4* vp = (const float4*)(Vb + (size_t)s * DOUT) + lane * 4;
            float4 v0 = vp[0];
            float4 v1 = vp[1];
            float4 v2 = vp[2];
            float4 v3 = vp[3];
            acc0 += p * v0.x; acc1 += p * v0.y; acc2 += p * v0.z; acc3 += p * v0.w;
            acc4 += p * v1.x; acc5 += p * v1.y; acc6 += p * v1.z; acc7 += p * v1.w;
            acc8 += p * v2.x; acc9 += p * v2.y; accA += p * v2.z; accB += p * v2.w;
            accC += p * v3.x; accD += p * v3.y; accE += p * v3.z; accF += p * v3.w;
        }
    }

    float inv = 1.f / psum;
    float4* op = (float4*)(Out + (size_t)q * DOUT) + lane * 4;
    op[0] = make_float4(acc0 * inv, acc1 * inv, acc2 * inv, acc3 * inv);
    op[1] = make_float4(acc4 * inv, acc5 * inv, acc6 * inv, acc7 * inv);
    op[2] = make_float4(acc8 * inv, acc9 * inv, accA * inv, accB * inv);
    op[3] = make_float4(accC * inv, accD * inv, accE * inv, accF * inv);
}

// ---------------------------------------------------------------------------
// Dense attention: ticket-queue persistent CTAs. R10-exact.
// ---------------------------------------------------------------------------
__global__ __launch_bounds__(256) void attn_dense_kernel(float* __restrict__ Out) {
    __shared__ float p_s[32][20];
    __shared__ float psum_s[DGRP];
    __shared__ int   qq_s[DGRP];
    __shared__ int   s_unit;

    int tid  = threadIdx.x;
    int warp = tid >> 5;
    int lane = tid & 31;

    while (true) {
        if (tid == 0) s_unit = atomicAdd(&g_ticket, 1);
        __syncthreads();
        int u = s_unit;
        if (u >= g_nunits) return;
        int enc = g_units[u];
        int b   = enc >> 16;
        int g   = (enc >> 4) & 0xFFF;
        int cq  = enc & 0xF;
        __syncthreads();

        int count = g_dcount[b];
        const float* Kb = g_K + (size_t)b * T_ * DA;
        const float* Vb = g_V + (size_t)b * T_ * DOUT;

        int ng = count - g * DGRP;
        if (ng > DGRP) ng = DGRP;

        if (tid < DGRP)
            qq_s[tid] = (tid < ng) ? g_dq[b * T_ + g * DGRP + tid] : 0;
        __syncthreads();

        int q0i = 2 * warp;
        int q1i = 2 * warp + 1;
        bool v0 = q0i < ng;
        bool v1 = q1i < ng;
        int gq0 = b * T_ + qq_s[v0 ? q0i : 0];
        int gq1 = b * T_ + qq_s[v1 ? q1i : 0];
        float qv0[8], qv1[8];
#pragma unroll
        for (int f = 0; f < 8; f++) {
            qv0[f] = g_Q[(size_t)gq0 * DA + f];
            qv1[f] = g_Q[(size_t)gq1 * DA + f];
        }
        float m0 = g_m[gq0];
        float m1 = g_m[gq1];
        float ps0 = 0.f, ps1 = 0.f;

        int col  = cq * 128 + warp * 16 + (lane & 15);
        int kpar = lane >> 4;
        float acc[DGRP];
#pragma unroll
        for (int j = 0; j < DGRP; j++) acc[j] = 0.f;

        for (int c = 0; c < T_ / 32; c++) {
            int k = c * 32 + lane;
            const float4* kp = (const float4*)(Kb + (size_t)k * DA);
            float4 k0 = kp[0];
            float4 k1 = kp[1];
            float d0 = qv0[0]*k0.x + qv0[1]*k0.y + qv0[2]*k0.z + qv0[3]*k0.w
                     + qv0[4]*k1.x + qv0[5]*k1.y + qv0[6]*k1.z + qv0[7]*k1.w;
            float d1 = qv1[0]*k0.x + qv1[1]*k0.y + qv1[2]*k0.z + qv1[3]*k0.w
                     + qv1[4]*k1.x + qv1[5]*k1.y + qv1[6]*k1.z + qv1[7]*k1.w;
            float e0 = d0 * d0; e0 = e0 * e0; e0 = e0 * e0;
            float e1 = d1 * d1; e1 = e1 * e1; e1 = e1 * e1;
            float p0 = v0 ? __expf(e0 - m0) : 0.f;
            float p1 = v1 ? __expf(e1 - m1) : 0.f;
            ps0 += p0;
            ps1 += p1;
            p_s[lane][q0i] = p0;
            p_s[lane][q1i] = p1;
            __syncthreads();

            const float* vptr = Vb + (size_t)(c * 32 + kpar) * DOUT + col;
#pragma unroll
            for (int kk2 = 0; kk2 < 16; kk2++) {
                int kk = 2 * kk2 + kpar;
                float v = vptr[(size_t)(2 * kk2) * DOUT];
                float pr[16];
                *(float4*)(pr)      = *(const float4*)(&p_s[kk][0]);
                *(float4*)(pr + 4)  = *(const float4*)(&p_s[kk][4]);
                *(float4*)(pr + 8)  = *(const float4*)(&p_s[kk][8]);
                *(float4*)(pr + 12) = *(const float4*)(&p_s[kk][12]);
#pragma unroll
                for (int j = 0; j < DGRP; j++)
                    acc[j] += pr[j] * v;
            }
            __syncthreads();
        }

#pragma unroll
        for (int off = 16; off >= 1; off >>= 1) {
            ps0 += __shfl_xor_sync(0xffffffffu, ps0, off);
            ps1 += __shfl_xor_sync(0xffffffffu, ps1, off);
        }
        if (lane == 0) {
            if (v0) psum_s[q0i] = ps0;
            if (v1) psum_s[q1i] = ps1;
        }
        __syncthreads();

#pragma unroll
        for (int j = 0; j < DGRP; j++)
            acc[j] += __shfl_xor_sync(0xffffffffu, acc[j], 16);

        if (kpar == 0) {
            for (int j = 0; j < ng; j++) {
                int gq = b * T_ + qq_s[j];
                Out[(size_t)gq * DOUT + col] = acc[j] / psum_s[j];
            }
        }
        __syncthreads();
    }
}

// ---------------------------------------------------------------------------
extern "C" void kernel_launch(void* const* d_in, const int* in_sizes, int n_in,
                              void* d_out, int out_size) {
    (void)in_sizes; (void)n_in; (void)out_size;
    const float* X  = (const float*)d_in[0];
    const float* Wq = (const float*)d_in[1];
    const float* Wk = (const float*)d_in[2];
    const float* Wv = (const float*)d_in[3];
    float* Out = (float*)d_out;

    vproj_kernel<<<dim3(DOUT / 128, (B_ * T_) / 128), 256>>>(X, Wv);
    qk_kernel<<<(B_ * T_) / 32, 256>>>(X, Wq, Wk);
    attn_sparse_kernel<<<(B_ * T_) / 8, 256>>>(Out);
    plan_kernel<<<1, 32>>>();
    attn_dense_kernel<<<DGRID, 256>>>(Out);
}

// round 16
// speedup vs baseline: 1.2350x; 1.0535x over previous
#include <cuda_runtime.h>
#include <math.h>

#define B_    8
#define T_    2048
#define DIN   512
#define DA    8
#define DOUT  512
#define NCAP  192         // survivor cap: dense path is cheaper above ~128
#define THR   16.0f       // exp(-16) ~ 1.1e-7 dropped-per-key bound
#define DGRP  16          // dense queries per group
#define NSPLIT 4          // column quarters per group
#define DGRID 512         // persistent dense CTAs

__device__ __align__(16) float g_Q[B_ * T_ * DA];
__device__ __align__(16) float g_K[B_ * T_ * DA];
__device__ __align__(16) float g_V[B_ * T_ * DOUT];
__device__ float g_m[B_ * T_];          // per-query max of d^8
__device__ int   g_dcount[B_];          // dense-queue counts
__device__ int   g_dq[B_ * T_];         // dense-queue (local q indices per batch)
__device__ int   g_units[B_ * (T_ / DGRP) * NSPLIT + 64];
__device__ int   g_nunits;
__device__ int   g_ticket;

// ---------------------------------------------------------------------------
// f32x2 packed helpers
// ---------------------------------------------------------------------------
__device__ __forceinline__ unsigned long long pack2(float lo, float hi) {
    unsigned long long d;
    asm("mov.b64 %0, {%1, %2};" : "=l"(d) : "f"(lo), "f"(hi));
    return d;
}
__device__ __forceinline__ unsigned long long fma2(unsigned long long a,
                                                   unsigned long long b,
                                                   unsigned long long c) {
    unsigned long long d;
    asm("fma.rn.f32x2 %0, %1, %2, %3;" : "=l"(d) : "l"(a), "l"(b), "l"(c));
    return d;
}
__device__ __forceinline__ void unpack2(unsigned long long v, float& lo, float& hi) {
    asm("mov.b64 {%0, %1}, %2;" : "=f"(lo), "=f"(hi) : "l"(v));
}

// ---------------------------------------------------------------------------
__global__ void plan_kernel() {
    if (threadIdx.x != 0) return;
    int total = 0;
    for (int b = 0; b < B_; b++) {
        int cnt = g_dcount[b];
        int groups = (cnt + DGRP - 1) / DGRP;
        for (int g = 0; g < groups; g++)
            for (int cq = 0; cq < NSPLIT; cq++)
                g_units[total++] = (b << 16) | (g << 4) | cq;
    }
    g_nunits = total;
    g_ticket = 0;
}

// ---------------------------------------------------------------------------
// V = X @ Wv with packed f32x2 FMAs (measured ~170us). Also zeroes the
// dense-queue counters (runs before attn_sparse in the same stream).
// ---------------------------------------------------------------------------
__global__ __launch_bounds__(256, 2) void vproj_kernel(const float* __restrict__ A,
                                                       const float* __restrict__ Bw) {
    __shared__ float As[16][132];
    __shared__ float Bs[16][128];

    int t  = threadIdx.x;
    int bm = blockIdx.y;
    int bn = blockIdx.x;
    int tr = t >> 4;
    int tc = t & 15;

    if (bm == 0 && bn == 0 && t < B_) g_dcount[t] = 0;

    const float* Ag = A + (size_t)bm * 128 * DIN;
    const float* Bg = Bw + (size_t)bn * 128;

    unsigned long long acc2[4][8];
#pragma unroll
    for (int p = 0; p < 4; p++)
#pragma unroll
        for (int j = 0; j < 8; j++) acc2[p][j] = 0ull;

    for (int kt = 0; kt < DIN; kt += 16) {
#pragma unroll
        for (int e = t; e < 512; e += 256) {
            int row = e >> 2;
            int cg  = (e & 3) << 2;
            float4 v = *(const float4*)(Ag + (size_t)row * DIN + kt + cg);
            As[cg + 0][row] = v.x;
            As[cg + 1][row] = v.y;
            As[cg + 2][row] = v.z;
            As[cg + 3][row] = v.w;
        }
#pragma unroll
        for (int e = t; e < 512; e += 256) {
            int row = e >> 5;
            int cg  = (e & 31) << 2;
            *(float4*)(&Bs[row][cg]) =
                *(const float4*)(Bg + (size_t)(kt + row) * DOUT + cg);
        }
        __syncthreads();

#pragma unroll
        for (int k = 0; k < 16; k++) {
            ulonglong2 a01 = *(const ulonglong2*)(&As[k][tr * 4]);
            ulonglong2 a23 = *(const ulonglong2*)(&As[k][tr * 4 + 64]);
            float4 bA = *(const float4*)(&Bs[k][tc * 4]);
            float4 bB = *(const float4*)(&Bs[k][tc * 4 + 64]);
            unsigned long long a2[4] = {a01.x, a01.y, a23.x, a23.y};
            unsigned long long b2[8];
            b2[0] = pack2(bA.x, bA.x); b2[1] = pack2(bA.y, bA.y);
            b2[2] = pack2(bA.z, bA.z); b2[3] = pack2(bA.w, bA.w);
            b2[4] = pack2(bB.x, bB.x); b2[5] = pack2(bB.y, bB.y);
            b2[6] = pack2(bB.z, bB.z); b2[7] = pack2(bB.w, bB.w);
#pragma unroll
            for (int p = 0; p < 4; p++)
#pragma unroll
                for (int j = 0; j < 8; j++)
                    acc2[p][j] = fma2(a2[p], b2[j], acc2[p][j]);
        }
        __syncthreads();
    }

#pragma unroll
    for (int p = 0; p < 4; p++) {
        int r0 = tr * 4 + (p >> 1) * 64 + (p & 1) * 2;
        float lo[8], hi[8];
#pragma unroll
        for (int j = 0; j < 8; j++) unpack2(acc2[p][j], lo[j], hi[j]);
        float* c0 = g_V + (size_t)(bm * 128 + r0) * DOUT + bn * 128;
        float* c1 = c0 + DOUT;
        *(float4*)(c0 + tc * 4)      = make_float4(lo[0], lo[1], lo[2], lo[3]);
        *(float4*)(c0 + tc * 4 + 64) = make_float4(lo[4], lo[5], lo[6], lo[7]);
        *(float4*)(c1 + tc * 4)      = make_float4(hi[0], hi[1], hi[2], hi[3]);
        *(float4*)(c1 + tc * 4 + 64) = make_float4(hi[4], hi[5], hi[6], hi[7]);
    }
}

// ---------------------------------------------------------------------------
// Q,K projections (measured ~35us). R10-exact.
// ---------------------------------------------------------------------------
__global__ __launch_bounds__(256) void qk_kernel(const float* __restrict__ X,
                                                 const float* __restrict__ Wq,
                                                 const float* __restrict__ Wk) {
    int warp = threadIdx.x >> 5;
    int lane = threadIdx.x & 31;
    int tok0 = blockIdx.x * 32 + warp * 4;

    float aq[4][8], ak[4][8];
#pragma unroll
    for (int t = 0; t < 4; t++)
#pragma unroll
        for (int f = 0; f < 8; f++) { aq[t][f] = 0.f; ak[t][f] = 0.f; }

#pragma unroll 4
    for (int d = lane; d < DIN; d += 32) {
        float xv[4];
#pragma unroll
        for (int t = 0; t < 4; t++) xv[t] = X[(size_t)(tok0 + t) * DIN + d];
        float4 q0 = *(const float4*)(Wq + (size_t)d * 8);
        float4 q1 = *(const float4*)(Wq + (size_t)d * 8 + 4);
        float4 k0 = *(const float4*)(Wk + (size_t)d * 8);
        float4 k1 = *(const float4*)(Wk + (size_t)d * 8 + 4);
#pragma unroll
        for (int t = 0; t < 4; t++) {
            aq[t][0] += xv[t] * q0.x; aq[t][1] += xv[t] * q0.y;
            aq[t][2] += xv[t] * q0.z; aq[t][3] += xv[t] * q0.w;
            aq[t][4] += xv[t] * q1.x; aq[t][5] += xv[t] * q1.y;
            aq[t][6] += xv[t] * q1.z; aq[t][7] += xv[t] * q1.w;
            ak[t][0] += xv[t] * k0.x; ak[t][1] += xv[t] * k0.y;
            ak[t][2] += xv[t] * k0.z; ak[t][3] += xv[t] * k0.w;
            ak[t][4] += xv[t] * k1.x; ak[t][5] += xv[t] * k1.y;
            ak[t][6] += xv[t] * k1.z; ak[t][7] += xv[t] * k1.w;
        }
    }

#pragma unroll
    for (int t = 0; t < 4; t++) {
#pragma unroll
        for (int f = 0; f < 8; f++) {
#pragma unroll
            for (int off = 16; off >= 1; off >>= 1) {
                aq[t][f] += __shfl_xor_sync(0xffffffffu, aq[t][f], off);
                ak[t][f] += __shfl_xor_sync(0xffffffffu, ak[t][f], off);
            }
        }
        if (lane == 0) {
            float* qo = g_Q + (size_t)(tok0 + t) * 8;
            float* ko = g_K + (size_t)(tok0 + t) * 8;
            *(float4*)(qo)     = make_float4(aq[t][0], aq[t][1], aq[t][2], aq[t][3]);
            *(float4*)(qo + 4) = make_float4(aq[t][4], aq[t][5], aq[t][6], aq[t][7]);
            *(float4*)(ko)     = make_float4(ak[t][0], ak[t][1], ak[t][2], ak[t][3]);
            *(float4*)(ko + 4) = make_float4(ak[t][4], ak[t][5], ak[t][6], ak[t][7]);
        }
    }
}

// ---------------------------------------------------------------------------
// Sparse attention — NO per-thread score array (the old s8v[64] = 256B of
// local memory per thread; ~400MB chip-wide local traffic and a 55%
// occupancy cap were the measured profile). Pass 1: max only. Pass 2:
// recompute d8 (coalesced LDG, high MLP), count survivors, build a uniform
// 64-bit chunk-occupancy mask (2 regs). Pass 3: visit ONLY nonempty chunks
// (typically 1-3), recompute d8 there, ballot-walk gather. Arithmetic is
// bit-identical to R10/R15 (same inputs, same ops).
// ---------------------------------------------------------------------------
__global__ __launch_bounds__(256) void attn_sparse_kernel(float* __restrict__ Out) {
    int warp = threadIdx.x >> 5;
    int lane = threadIdx.x & 31;
    int q    = blockIdx.x * 8 + warp;
    int b    = q >> 11;
    const float* Kb = g_K + (size_t)b * T_ * DA;
    const float* Vb = g_V + (size_t)b * T_ * DOUT;

    float4 qa = *(const float4*)(g_Q + (size_t)q * DA);
    float4 qb = *(const float4*)(g_Q + (size_t)q * DA + 4);

    // ---- Pass 1: row max (no storage) ----
    float m = -INFINITY;
#pragma unroll 1
    for (int i = 0; i < 64; i++) {
        int s = i * 32 + lane;
        const float4* kp = (const float4*)(Kb + (size_t)s * DA);
        float4 k0 = kp[0];
        float4 k1 = kp[1];
        float d = qa.x * k0.x + qa.y * k0.y + qa.z * k0.z + qa.w * k0.w
                + qb.x * k1.x + qb.y * k1.y + qb.z * k1.z + qb.w * k1.w;
        float d2 = d * d;
        float d4 = d2 * d2;
        float d8 = d4 * d4;
        m = fmaxf(m, d8);
    }
#pragma unroll
    for (int off = 16; off >= 1; off >>= 1)
        m = fmaxf(m, __shfl_xor_sync(0xffffffffu, m, off));

    if (lane == 0) g_m[q] = m;

    float thr = m - THR;

    // ---- Pass 2: recompute, count, build uniform chunk mask ----
    int n = 0;
    unsigned cm0 = 0, cm1 = 0;    // chunk-occupancy bits, identical all lanes
#pragma unroll 1
    for (int i = 0; i < 64; i++) {
        int s = i * 32 + lane;
        const float4* kp = (const float4*)(Kb + (size_t)s * DA);
        float4 k0 = kp[0];
        float4 k1 = kp[1];
        float d = qa.x * k0.x + qa.y * k0.y + qa.z * k0.z + qa.w * k0.w
                + qb.x * k1.x + qb.y * k1.y + qb.z * k1.z + qb.w * k1.w;
        float d2 = d * d;
        float d4 = d2 * d2;
        float d8 = d4 * d4;
        unsigned ball = __ballot_sync(0xffffffffu, d8 > thr);
        n += __popc(ball);
        if (ball) {
            if (i < 32) cm0 |= 1u << i;
            else        cm1 |= 1u << (i - 32);
        }
    }

    if (n > NCAP) {
        if (lane == 0) {
            int idx = atomicAdd(&g_dcount[b], 1);
            g_dq[b * T_ + idx] = q & (T_ - 1);
        }
        return;
    }

    // ---- Pass 3: gather over nonempty chunks only ----
    float acc0 = 0.f, acc1 = 0.f, acc2 = 0.f, acc3 = 0.f;
    float acc4 = 0.f, acc5 = 0.f, acc6 = 0.f, acc7 = 0.f;
    float acc8 = 0.f, acc9 = 0.f, accA = 0.f, accB = 0.f;
    float accC = 0.f, accD = 0.f, accE = 0.f, accF = 0.f;
    float psum = 0.f;

#pragma unroll 1
    for (int w = 0; w < 2; w++) {
        unsigned cm = (w == 0) ? cm0 : cm1;
        while (cm) {
            int i = __ffs(cm) - 1 + w * 32;
            cm &= cm - 1;
            int s = i * 32 + lane;
            const float4* kp = (const float4*)(Kb + (size_t)s * DA);
            float4 k0 = kp[0];
            float4 k1 = kp[1];
            float d = qa.x * k0.x + qa.y * k0.y + qa.z * k0.z + qa.w * k0.w
                    + qb.x * k1.x + qb.y * k1.y + qb.z * k1.z + qb.w * k1.w;
            float d2 = d * d;
            float d4 = d2 * d2;
            float d8 = d4 * d4;
            unsigned ball = __ballot_sync(0xffffffffu, d8 > thr);
            while (ball) {
                int src = __ffs(ball) - 1;
                ball &= ball - 1;
                float d8s = __shfl_sync(0xffffffffu, d8, src);
                float p = __expf(d8s - m);     // identical in all lanes
                psum += p;
                int sk = i * 32 + src;
                const float4* vp = (const float4*)(Vb + (size_t)sk * DOUT) + lane * 4;
                float4 v0 = vp[0];
                float4 v1 = vp[1];
                float4 v2 = vp[2];
                float4 v3 = vp[3];
                acc0 += p * v0.x; acc1 += p * v0.y; acc2 += p * v0.z; acc3 += p * v0.w;
                acc4 += p * v1.x; acc5 += p * v1.y; acc6 += p * v1.z; acc7 += p * v1.w;
                acc8 += p * v2.x; acc9 += p * v2.y; accA += p * v2.z; accB += p * v2.w;
                accC += p * v3.x; accD += p * v3.y; accE += p * v3.z; accF += p * v3.w;
            }
        }
    }

    float inv = 1.f / psum;
    float4* op = (float4*)(Out + (size_t)q * DOUT) + lane * 4;
    op[0] = make_float4(acc0 * inv, acc1 * inv, acc2 * inv, acc3 * inv);
    op[1] = make_float4(acc4 * inv, acc5 * inv, acc6 * inv, acc7 * inv);
    op[2] = make_float4(acc8 * inv, acc9 * inv, accA * inv, accB * inv);
    op[3] = make_float4(accC * inv, accD * inv, accE * inv, accF * inv);
}

// ---------------------------------------------------------------------------
// Dense attention: ticket-queue persistent CTAs. R10-exact.
// ---------------------------------------------------------------------------
__global__ __launch_bounds__(256) void attn_dense_kernel(float* __restrict__ Out) {
    __shared__ float p_s[32][20];
    __shared__ float psum_s[DGRP];
    __shared__ int   qq_s[DGRP];
    __shared__ int   s_unit;

    int tid  = threadIdx.x;
    int warp = tid >> 5;
    int lane = tid & 31;

    while (true) {
        if (tid == 0) s_unit = atomicAdd(&g_ticket, 1);
        __syncthreads();
        int u = s_unit;
        if (u >= g_nunits) return;
        int enc = g_units[u];
        int b   = enc >> 16;
        int g   = (enc >> 4) & 0xFFF;
        int cq  = enc & 0xF;
        __syncthreads();

        int count = g_dcount[b];
        const float* Kb = g_K + (size_t)b * T_ * DA;
        const float* Vb = g_V + (size_t)b * T_ * DOUT;

        int ng = count - g * DGRP;
        if (ng > DGRP) ng = DGRP;

        if (tid < DGRP)
            qq_s[tid] = (tid < ng) ? g_dq[b * T_ + g * DGRP + tid] : 0;
        __syncthreads();

        int q0i = 2 * warp;
        int q1i = 2 * warp + 1;
        bool v0 = q0i < ng;
        bool v1 = q1i < ng;
        int gq0 = b * T_ + qq_s[v0 ? q0i : 0];
        int gq1 = b * T_ + qq_s[v1 ? q1i : 0];
        float qv0[8], qv1[8];
#pragma unroll
        for (int f = 0; f < 8; f++) {
            qv0[f] = g_Q[(size_t)gq0 * DA + f];
            qv1[f] = g_Q[(size_t)gq1 * DA + f];
        }
        float m0 = g_m[gq0];
        float m1 = g_m[gq1];
        float ps0 = 0.f, ps1 = 0.f;

        int col  = cq * 128 + warp * 16 + (lane & 15);
        int kpar = lane >> 4;
        float acc[DGRP];
#pragma unroll
        for (int j = 0; j < DGRP; j++) acc[j] = 0.f;

        for (int c = 0; c < T_ / 32; c++) {
            int k = c * 32 + lane;
            const float4* kp = (const float4*)(Kb + (size_t)k * DA);
            float4 k0 = kp[0];
            float4 k1 = kp[1];
            float d0 = qv0[0]*k0.x + qv0[1]*k0.y + qv0[2]*k0.z + qv0[3]*k0.w
                     + qv0[4]*k1.x + qv0[5]*k1.y + qv0[6]*k1.z + qv0[7]*k1.w;
            float d1 = qv1[0]*k0.x + qv1[1]*k0.y + qv1[2]*k0.z + qv1[3]*k0.w
                     + qv1[4]*k1.x + qv1[5]*k1.y + qv1[6]*k1.z + qv1[7]*k1.w;
            float e0 = d0 * d0; e0 = e0 * e0; e0 = e0 * e0;
            float e1 = d1 * d1; e1 = e1 * e1; e1 = e1 * e1;
            float p0 = v0 ? __expf(e0 - m0) : 0.f;
            float p1 = v1 ? __expf(e1 - m1) : 0.f;
            ps0 += p0;
            ps1 += p1;
            p_s[lane][q0i] = p0;
            p_s[lane][q1i] = p1;
            __syncthreads();

            const float* vptr = Vb + (size_t)(c * 32 + kpar) * DOUT + col;
#pragma unroll
            for (int kk2 = 0; kk2 < 16; kk2++) {
                int kk = 2 * kk2 + kpar;
                float v = vptr[(size_t)(2 * kk2) * DOUT];
                float pr[16];
                *(float4*)(pr)      = *(const float4*)(&p_s[kk][0]);
                *(float4*)(pr + 4)  = *(const float4*)(&p_s[kk][4]);
                *(float4*)(pr + 8)  = *(const float4*)(&p_s[kk][8]);
                *(float4*)(pr + 12) = *(const float4*)(&p_s[kk][12]);
#pragma unroll
                for (int j = 0; j < DGRP; j++)
                    acc[j] += pr[j] * v;
            }
            __syncthreads();
        }

#pragma unroll
        for (int off = 16; off >= 1; off >>= 1) {
            ps0 += __shfl_xor_sync(0xffffffffu, ps0, off);
            ps1 += __shfl_xor_sync(0xffffffffu, ps1, off);
        }
        if (lane == 0) {
            if (v0) psum_s[q0i] = ps0;
            if (v1) psum_s[q1i] = ps1;
        }
        __syncthreads();

#pragma unroll
        for (int j = 0; j < DGRP; j++)
            acc[j] += __shfl_xor_sync(0xffffffffu, acc[j], 16);

        if (kpar == 0) {
            for (int j = 0; j < ng; j++) {
                int gq = b * T_ + qq_s[j];
                Out[(size_t)gq * DOUT + col] = acc[j] / psum_s[j];
            }
        }
        __syncthreads();
    }
}

// ---------------------------------------------------------------------------
extern "C" void kernel_launch(void* const* d_in, const int* in_sizes, int n_in,
                              void* d_out, int out_size) {
    (void)in_sizes; (void)n_in; (void)out_size;
    const float* X  = (const float*)d_in[0];
    const float* Wq = (const float*)d_in[1];
    const float* Wk = (const float*)d_in[2];
    const float* Wv = (const float*)d_in[3];
    float* Out = (float*)d_out;

    vproj_kernel<<<dim3(DOUT / 128, (B_ * T_) / 128), 256>>>(X, Wv);
    qk_kernel<<<(B_ * T_) / 32, 256>>>(X, Wq, Wk);
    attn_sparse_kernel<<<(B_ * T_) / 8, 256>>>(Out);
    plan_kernel<<<1, 32>>>();
    attn_dense_kernel<<<DGRID, 256>>>(Out);
}